// round 2
// baseline (speedup 1.0000x reference)
#include <cuda_runtime.h>
#include <cstdint>

// ---------------------------------------------------------------------------
// RNN_arch_2: 16-step vanilla RNN, B=16384, D_IN=64, D_H=256, D_MID=64, D_OUT=4
// One block owns 64 batch rows; h lives in SMEM across all 16 steps.
// Main GEMM per step: [64 x 256] += [64 x 320] @ W^T via packed fp32x2 FMA
// (FFMA2, 2 fp32 lanes/instr), weights streamed L2->SMEM with cp.async
// double buffering. h2o GEMM reads W_h2o straight from L1 (warp-broadcast).
// ---------------------------------------------------------------------------

#define T_STEPS 16
#define BATCH   16384
#define DIN     64
#define DH      256
#define DMID    64
#define DOUT    4
#define KTOT    (DIN + DH)      // 320

#define BT      64              // batch rows per block
#define NTH     256             // threads per block
#define KC      32              // K-chunk width
#define NCHUNK  (KTOT / KC)     // 10

// SMEM strides (floats); multiples of 4 keep 16B alignment for vector ops.
#define A_STRIDE    68          // A_s[k][row], 64 rows + pad
#define WC_STRIDE   36          // W chunk [j][kk], KC + pad
#define MID_STRIDE  65

#define A_ELEMS     (KTOT * A_STRIDE)       // 21760
#define WBUF_ELEMS  (DH * WC_STRIDE)        // 9216
#define WAREA_ELEMS (2 * WBUF_ELEMS)        // 18432
#define MID_ELEMS   (BT * MID_STRIDE)       // 4160
#define WFC_ELEMS   (DOUT * DMID)           // 256

#define OFF_A    0
#define OFF_W    (OFF_A + A_ELEMS)
#define OFF_MID  (OFF_W + WAREA_ELEMS)
#define OFF_WFC  (OFF_MID + MID_ELEMS)
#define OFF_BFC  (OFF_WFC + WFC_ELEMS)
#define SMEM_FLOATS (OFF_BFC + DOUT)
#define SMEM_BYTES  (SMEM_FLOATS * 4)       // ~178 KB

// ----------------------------- PTX helpers ---------------------------------

__device__ __forceinline__ unsigned long long pack2(float lo, float hi) {
    unsigned long long r;
    asm("mov.b64 %0, {%1, %2};" : "=l"(r) : "f"(lo), "f"(hi));
    return r;
}
__device__ __forceinline__ void unpack2(unsigned long long p, float& lo, float& hi) {
    asm("mov.b64 {%0, %1}, %2;" : "=f"(lo), "=f"(hi) : "l"(p));
}
// Packed fp32x2 FMA: d = a * b + c  (two fp32 lanes per instruction -> FFMA2)
__device__ __forceinline__ unsigned long long fma2(unsigned long long a,
                                                   unsigned long long b,
                                                   unsigned long long c) {
    unsigned long long d;
    asm("fma.rn.f32x2 %0, %1, %2, %3;" : "=l"(d) : "l"(a), "l"(b), "l"(c));
    return d;
}

__device__ __forceinline__ void cp_async16(uint32_t smem_addr, const void* gptr) {
    asm volatile("cp.async.cg.shared.global [%0], [%1], 16;\n"
                 :: "r"(smem_addr), "l"(gptr));
}
#define CP_COMMIT() asm volatile("cp.async.commit_group;\n" ::: "memory")
#define CP_WAIT(n)  asm volatile("cp.async.wait_group %0;\n" :: "n"(n) : "memory")

// Fast, accurate tanh: 1 - 2/(e^{2x}+1).  Abs err ~1e-7; saturates correctly.
__device__ __forceinline__ float tanh_fast(float v) {
    float e = __expf(2.0f * v);
    return 1.0f - __fdividef(2.0f, e + 1.0f);
}

// ----------------------------- kernel --------------------------------------

__global__ void __launch_bounds__(NTH, 1)
rnn16_kernel(const float* __restrict__ x,      const float* __restrict__ hc1,
             const float* __restrict__ W_i2h,  const float* __restrict__ b_i2h,
             const float* __restrict__ W_h2h,  const float* __restrict__ b_h2h,
             const float* __restrict__ W_h2o,  const float* __restrict__ b_h2o,
             const float* __restrict__ W_fc,   const float* __restrict__ b_fc,
             float* __restrict__ out_seq,      float* __restrict__ h_final)
{
    extern __shared__ float smem[];
    float* A_s   = smem + OFF_A;    // [k][row], k in [0,320): 0..63 = x_t, 64.. = h
    float* Wbuf  = smem + OFF_W;    // 2 cp.async chunk buffers
    float* mid_s = smem + OFF_MID;  // [row][m]
    float* wfc_s = smem + OFF_WFC;
    float* bfc_s = smem + OFF_BFC;

    const int tid = threadIdx.x;
    const int tc  = tid & 31;       // lane (column group)
    const int tr  = tid >> 5;       // warp (row group)
    const int r0  = tr * 8;         // this thread's 8 rows (4 fp32x2 pairs)
    const int rowbase = blockIdx.x * BT;

    // ---- W chunk streamer: chunk c covers global k in [c*32, c*32+32) -----
    auto issue_chunk = [&](int c, float* dst) {
        const int k0 = c * KC;
        const float* src;
        int rs;
        if (k0 < DIN) { src = W_i2h + k0; rs = DIN; }
        else          { src = W_h2h + (k0 - DIN); rs = DH; }
        #pragma unroll
        for (int i = 0; i < 8; ++i) {
            int e = tid + NTH * i;          // float4 index within chunk (2048)
            int j = e >> 3;                 // hidden col 0..255
            int q = e & 7;                  // k_local / 4
            uint32_t d = (uint32_t)__cvta_generic_to_shared(dst + j * WC_STRIDE + q * 4);
            cp_async16(d, src + (size_t)j * rs + q * 4);
        }
    };

    // Prefetch W chunk 0 of step 0 immediately.
    issue_chunk(0, Wbuf);
    CP_COMMIT();

    // fc weights + biases to smem
    wfc_s[tid] = W_fc[tid];                 // 4*64 = 256 floats
    if (tid < DOUT) bfc_s[tid] = b_fc[tid];

    // Per-thread column biases (8 cols: j = 2*tc + off + 64*n2)
    float bias[4][2];
    #pragma unroll
    for (int n2 = 0; n2 < 4; ++n2)
        #pragma unroll
        for (int off = 0; off < 2; ++off) {
            int j = 2 * tc + off + 64 * n2;
            bias[n2][off] = b_i2h[j] + b_h2h[j];
        }
    const float bmid0 = b_h2o[2 * tc];
    const float bmid1 = b_h2o[2 * tc + 1];

    // hc1 -> A_s h-region (transposed: [64+j][r])
    #pragma unroll
    for (int i = tid * 4; i < BT * DH; i += NTH * 4) {
        float4 v = *reinterpret_cast<const float4*>(&hc1[(size_t)rowbase * DH + i]);
        int r = i >> 8, j = i & 255;
        A_s[(DIN + j + 0) * A_STRIDE + r] = v.x;
        A_s[(DIN + j + 1) * A_STRIDE + r] = v.y;
        A_s[(DIN + j + 2) * A_STRIDE + r] = v.z;
        A_s[(DIN + j + 3) * A_STRIDE + r] = v.w;
    }
    // x_0 -> A_s x-region (transposed: [k][r])
    {
        const float* xp = x + (size_t)rowbase * DIN;
        #pragma unroll
        for (int i = tid * 4; i < BT * DIN; i += NTH * 4) {
            float4 v = *reinterpret_cast<const float4*>(&xp[i]);
            int r = i >> 6, k = i & 63;
            A_s[(k + 0) * A_STRIDE + r] = v.x;
            A_s[(k + 1) * A_STRIDE + r] = v.y;
            A_s[(k + 2) * A_STRIDE + r] = v.z;
            A_s[(k + 3) * A_STRIDE + r] = v.w;
        }
    }
    // (the first __syncthreads inside the chunk loop guards these writes)

    for (int t = 0; t < T_STEPS; ++t) {
        // ---- main GEMM: C[64 x 256] over K = 320 ---------------------------
        // acc[(n2*2+off)*4 + rp] packs rows (r0+2rp, r0+2rp+1) for
        // col j = 2*tc + off + 64*n2 as fp32x2.
        unsigned long long acc[32];
        #pragma unroll
        for (int n2 = 0; n2 < 4; ++n2)
            #pragma unroll
            for (int off = 0; off < 2; ++off)
                #pragma unroll
                for (int rp = 0; rp < 4; ++rp)
                    acc[(n2 * 2 + off) * 4 + rp] = pack2(bias[n2][off], bias[n2][off]);

        #pragma unroll 1
        for (int c = 0; c < NCHUNK; ++c) {
            if (c + 1 < NCHUNK) {
                issue_chunk(c + 1, Wbuf + ((c + 1) & 1) * WBUF_ELEMS);
                CP_COMMIT();
                CP_WAIT(1);
            } else {
                CP_WAIT(0);
            }
            __syncthreads();  // chunk c visible; also guards A_s writes

            const float* wb = Wbuf + (c & 1) * WBUF_ELEMS;
            const int kbase = c * KC;
            #pragma unroll
            for (int kk = 0; kk < KC; kk += 4) {
                float4 wv[4][2];
                #pragma unroll
                for (int n2 = 0; n2 < 4; ++n2)
                    #pragma unroll
                    for (int off = 0; off < 2; ++off) {
                        int j = 2 * tc + off + 64 * n2;
                        wv[n2][off] = *reinterpret_cast<const float4*>(&wb[j * WC_STRIDE + kk]);
                    }
                #pragma unroll
                for (int dk = 0; dk < 4; ++dk) {
                    const float* ap = &A_s[(kbase + kk + dk) * A_STRIDE + r0];
                    ulonglong2 pA = *reinterpret_cast<const ulonglong2*>(ap);
                    ulonglong2 pB = *reinterpret_cast<const ulonglong2*>(ap + 4);
                    unsigned long long a2[4] = { pA.x, pA.y, pB.x, pB.y };
                    #pragma unroll
                    for (int n2 = 0; n2 < 4; ++n2)
                        #pragma unroll
                        for (int off = 0; off < 2; ++off) {
                            float w = reinterpret_cast<const float*>(&wv[n2][off])[dk];
                            unsigned long long w2 = pack2(w, w);
                            #pragma unroll
                            for (int rp = 0; rp < 4; ++rp)
                                acc[(n2 * 2 + off) * 4 + rp] =
                                    fma2(a2[rp], w2, acc[(n2 * 2 + off) * 4 + rp]);
                        }
                }
            }
            __syncthreads();  // done reading buf[c&1] before it is re-filled
        }

        // ---- h_new = tanh(C) -> A_s h-region -------------------------------
        #pragma unroll
        for (int n2 = 0; n2 < 4; ++n2)
            #pragma unroll
            for (int off = 0; off < 2; ++off) {
                int j = 2 * tc + off + 64 * n2;
                #pragma unroll
                for (int rp = 0; rp < 4; ++rp) {
                    float lo, hi;
                    unpack2(acc[(n2 * 2 + off) * 4 + rp], lo, hi);
                    float2 h2;
                    h2.x = tanh_fast(lo);
                    h2.y = tanh_fast(hi);
                    *reinterpret_cast<float2*>(&A_s[(DIN + j) * A_STRIDE + r0 + 2 * rp]) = h2;
                }
            }
        __syncthreads();

        // Prefetch next step's first W chunk now: the double-buffer region is
        // idle for the rest of this step, giving the cp.async the whole
        // h2o + fc + x-load tail to land.
        if (t + 1 < T_STEPS) {
            issue_chunk(0, Wbuf);
            CP_COMMIT();
        }

        // ---- h2o GEMM: mid[64 x 64] = tanh(h_new @ W_h2o^T + b) ------------
        // W_h2o rows (2*tc, 2*tc+1) are identical across warps -> L1 broadcast.
        {
            unsigned long long a0[4], a1[4];
            #pragma unroll
            for (int rp = 0; rp < 4; ++rp) {
                a0[rp] = pack2(bmid0, bmid0);
                a1[rp] = pack2(bmid1, bmid1);
            }
            const int m0 = 2 * tc;
            const float4* w0p = reinterpret_cast<const float4*>(W_h2o + (size_t)m0 * DH);
            const float4* w1p = reinterpret_cast<const float4*>(W_h2o + (size_t)(m0 + 1) * DH);
            #pragma unroll 2
            for (int k = 0; k < DH; k += 4) {
                float4 w0 = __ldg(&w0p[k >> 2]);
                float4 w1 = __ldg(&w1p[k >> 2]);
                #pragma unroll
                for (int dk = 0; dk < 4; ++dk) {
                    const float* ap = &A_s[(DIN + k + dk) * A_STRIDE + r0];
                    ulonglong2 pA = *reinterpret_cast<const ulonglong2*>(ap);
                    ulonglong2 pB = *reinterpret_cast<const ulonglong2*>(ap + 4);
                    unsigned long long a2[4] = { pA.x, pA.y, pB.x, pB.y };
                    float f0 = reinterpret_cast<const float*>(&w0)[dk];
                    float f1 = reinterpret_cast<const float*>(&w1)[dk];
                    unsigned long long w20 = pack2(f0, f0);
                    unsigned long long w21 = pack2(f1, f1);
                    #pragma unroll
                    for (int rp = 0; rp < 4; ++rp) {
                        a0[rp] = fma2(a2[rp], w20, a0[rp]);
                        a1[rp] = fma2(a2[rp], w21, a1[rp]);
                    }
                }
            }
            #pragma unroll
            for (int rp = 0; rp < 4; ++rp) {
                float lo, hi;
                unpack2(a0[rp], lo, hi);
                mid_s[(r0 + 2 * rp + 0) * MID_STRIDE + m0] = tanh_fast(lo);
                mid_s[(r0 + 2 * rp + 1) * MID_STRIDE + m0] = tanh_fast(hi);
                unpack2(a1[rp], lo, hi);
                mid_s[(r0 + 2 * rp + 0) * MID_STRIDE + m0 + 1] = tanh_fast(lo);
                mid_s[(r0 + 2 * rp + 1) * MID_STRIDE + m0 + 1] = tanh_fast(hi);
            }
        }
        __syncthreads();

        // ---- fc: out[r][o] = mid[r] @ W_fc[o]^T + b_fc ---------------------
        {
            int r = tid >> 2, o = tid & 3;
            float accf = bfc_s[o];
            #pragma unroll
            for (int m = 0; m < DMID; ++m)
                accf = fmaf(mid_s[r * MID_STRIDE + m], wfc_s[o * DMID + m], accf);
            out_seq[((size_t)t * BATCH + rowbase + r) * DOUT + o] = accf;
        }

        // ---- load x_{t+1} into A_s x-region (no reader until next c-loop) --
        if (t + 1 < T_STEPS) {
            const float* xp = x + (size_t)(t + 1) * BATCH * DIN + (size_t)rowbase * DIN;
            #pragma unroll
            for (int i = tid * 4; i < BT * DIN; i += NTH * 4) {
                float4 v = *reinterpret_cast<const float4*>(&xp[i]);
                int r = i >> 6, k = i & 63;
                A_s[(k + 0) * A_STRIDE + r] = v.x;
                A_s[(k + 1) * A_STRIDE + r] = v.y;
                A_s[(k + 2) * A_STRIDE + r] = v.z;
                A_s[(k + 3) * A_STRIDE + r] = v.w;
            }
        }
        // next iteration's first in-chunk-loop __syncthreads guards these
    }

    // ---- h_final: copy A_s h-region to gmem (coalesced) --------------------
    __syncthreads();
    #pragma unroll
    for (int i = tid * 4; i < BT * DH; i += NTH * 4) {
        int r = i >> 8, j = i & 255;
        float4 v;
        v.x = A_s[(DIN + j + 0) * A_STRIDE + r];
        v.y = A_s[(DIN + j + 1) * A_STRIDE + r];
        v.z = A_s[(DIN + j + 2) * A_STRIDE + r];
        v.w = A_s[(DIN + j + 3) * A_STRIDE + r];
        *reinterpret_cast<float4*>(&h_final[(size_t)(rowbase + r) * DH + j]) = v;
    }
}

// ----------------------------- launch wrapper -------------------------------

extern "C" void kernel_launch(void* const* d_in, const int* in_sizes, int n_in,
                              void* d_out, int out_size) {
    const float* x     = (const float*)d_in[0];
    const float* hc1   = (const float*)d_in[1];
    const float* W_i2h = (const float*)d_in[2];
    const float* b_i2h = (const float*)d_in[3];
    const float* W_h2h = (const float*)d_in[4];
    const float* b_h2h = (const float*)d_in[5];
    const float* W_h2o = (const float*)d_in[6];
    const float* b_h2o = (const float*)d_in[7];
    const float* W_fc  = (const float*)d_in[8];
    const float* b_fc  = (const float*)d_in[9];

    float* out = (float*)d_out;
    float* h_final = out + (size_t)T_STEPS * BATCH * DOUT;  // out_seq, then h_final

    cudaFuncSetAttribute(rnn16_kernel,
                         cudaFuncAttributeMaxDynamicSharedMemorySize,
                         (int)SMEM_BYTES);

    rnn16_kernel<<<BATCH / BT, NTH, SMEM_BYTES>>>(
        x, hc1, W_i2h, b_i2h, W_h2h, b_h2h, W_h2o, b_h2o, W_fc, b_fc,
        out, h_final);
}